// round 5
// baseline (speedup 1.0000x reference)
#include <cuda_runtime.h>
#include <mma.h>
#include <math.h>
#include <cstdint>

using namespace nvcuda;

// Problem constants
constexpr int cNB   = 512;
constexpr int cMS   = 8;
constexpr int cT    = 64;
constexpr int cIN   = 360;
constexpr int cH    = 230;
constexpr int cHP   = 232;           // padded hidden (16B-aligned, mma K pad)
constexpr int cOUT  = 53;
constexpr int cENT  = 8;
constexpr int cB    = cNB * cMS;     // 4096
constexpr int c3H   = 3 * cH;        // 690
constexpr int c2H   = 2 * cH;        // 460
constexpr size_t cTB = (size_t)cT * cB;   // 262144

constexpr int cGP   = 240;           // per-gate padded width in Wt
constexpr int cNW   = 3 * cGP;       // 720 (Wt n-dim)
constexpr int BT    = 64;            // batch tile per GRU CTA

// ---------------------------------------------------------------------------
// Scratch
// ---------------------------------------------------------------------------
static __device__ float g_xg_f[(size_t)cT * cB * c3H];  // [T][B][3H]
static __device__ float g_xg_r[(size_t)cT * cB * c3H];
static __device__ float g_out [(size_t)cT * cB * c2H];  // [T][B][2H]
static __device__ float g_u   [(size_t)cT * cB * c2H];
static __device__ float g_Wt  [2][232 * cNW];           // k-major padded tf32 W_hh
static __device__ float g_score[(size_t)cB * cT];
static __device__ float g_alpha[(size_t)cB * cT];
static __device__ float g_wv  [(size_t)cB * c2H];
static __device__ float g_u2  [(size_t)cB * c2H];
static __device__ float g_s2  [cB];
static __device__ float g_sent[(size_t)cNB * c2H];

// ---------------------------------------------------------------------------
// Helpers
// ---------------------------------------------------------------------------
__device__ __forceinline__ float to_tf32(float x) {
    float r;
    asm("cvt.rna.tf32.f32 %0, %1;\n" : "=f"(r) : "f"(x));
    return r;
}
__device__ __forceinline__ float sigmoidf(float x) {
    return 1.f / (1.f + expf(-x));
}
__device__ __forceinline__ unsigned int smem_u32(const void* p) {
    return (unsigned int)__cvta_generic_to_shared(p);
}
__device__ __forceinline__ void cp16(unsigned int d, const void* s, int srcsize) {
    asm volatile("cp.async.cg.shared.global [%0], [%1], 16, %2;\n"
                 :: "r"(d), "l"(s), "r"(srcsize));
}
__device__ __forceinline__ void cp_commit() {
    asm volatile("cp.async.commit_group;\n");
}
template <int N>
__device__ __forceinline__ void cp_wait() {
    asm volatile("cp.async.wait_group %0;\n" :: "n"(N));
}

typedef wmma::fragment<wmma::matrix_a, 16, 16, 8, wmma::precision::tf32, wmma::row_major> FragA;
typedef wmma::fragment<wmma::matrix_b, 16, 16, 8, wmma::precision::tf32, wmma::col_major> FragBc;
typedef wmma::fragment<wmma::matrix_b, 16, 16, 8, wmma::precision::tf32, wmma::row_major> FragBr;
typedef wmma::fragment<wmma::accumulator, 16, 16, 8, float> FragC;

template <class F>
__device__ __forceinline__ void cvt_frag(F& f) {
    #pragma unroll
    for (int i = 0; i < f.num_elements; i++) f.x[i] = to_tf32(f.x[i]);
}

// ---------------------------------------------------------------------------
// Utility kernels
// ---------------------------------------------------------------------------
__global__ void zero_out_kernel(float* p, int n) {
    int i = blockIdx.x * blockDim.x + threadIdx.x;
    if (i < n) p[i] = 0.f;
}

// Pre-transpose W_hh into k-major, gate-padded, tf32-rounded layout:
// g_Wt[dir][k][g*240 + j] = tf32(Whh[g*230 + j][k]); zero padding elsewhere.
__global__ void wt_prep_kernel(const float* __restrict__ Whhf,
                               const float* __restrict__ Whhr) {
    int i = blockIdx.x * blockDim.x + threadIdx.x;
    if (i >= 2 * 232 * cNW) return;
    int dir = i / (232 * cNW);
    int r = i % (232 * cNW);
    int k = r / cNW, n = r % cNW;
    int g = n / cGP, j = n % cGP;
    const float* W = dir ? Whhr : Whhf;
    float v = 0.f;
    if (j < cH && k < cH) v = to_tf32(W[(size_t)(g * cH + j) * cH + k]);
    g_Wt[dir][k * cNW + n] = v;
}

// ---------------------------------------------------------------------------
// Input projection: C[M=262144, N=690] = bag @ W^T + b  (TN), row remap.
// 128x64 tile, BK=32, 2-stage cp.async, 8 warps x (32x32).
// ---------------------------------------------------------------------------
__global__ void __launch_bounds__(256, 2) iproj_kernel(
    const float* __restrict__ bag,
    const float* __restrict__ Wf, const float* __restrict__ bf,
    const float* __restrict__ Wr, const float* __restrict__ br)
{
    const int z = blockIdx.z;
    const float* __restrict__ W    = z ? Wr : Wf;
    const float* __restrict__ bias = z ? br : bf;
    float* __restrict__ dst        = z ? g_xg_r : g_xg_f;

    extern __shared__ float sm[];
    float* As = sm;            // [2][128][36]
    float* Bs = sm + 9216;     // [2][64][36]
    float* Cs = sm;            // [128][68]

    const int n0 = blockIdx.x * 64;
    const int m0 = blockIdx.y * 128;
    const int tid = threadIdx.x;
    const int wid = tid >> 5;
    const int wm = wid & 3;
    const int wn = wid >> 2;

    constexpr int KT = (cIN + 31) / 32;   // 12

    FragC acc[2][2];
    #pragma unroll
    for (int i = 0; i < 2; i++)
        #pragma unroll
        for (int j = 0; j < 2; j++) wmma::fill_fragment(acc[i][j], 0.f);

    auto load_stage = [&](int st, int k0) {
        float* A = As + st * 4608;
        float* B = Bs + st * 2304;
        #pragma unroll
        for (int q = 0; q < 4; q++) {
            int idx = q * 256 + tid;
            int r = idx >> 3, c4 = idx & 7;
            int k = k0 + c4 * 4;
            cp16(smem_u32(&A[r * 36 + c4 * 4]),
                 bag + (size_t)(m0 + r) * cIN + min(k, cIN - 4),
                 (k + 4 <= cIN) ? 16 : 0);
        }
        #pragma unroll
        for (int q = 0; q < 2; q++) {
            int idx = q * 256 + tid;
            int n = idx >> 3, c4 = idx & 7;
            int k = k0 + c4 * 4;
            int nn = min(n0 + n, c3H - 1);
            cp16(smem_u32(&B[n * 36 + c4 * 4]),
                 W + (size_t)nn * cIN + min(k, cIN - 4),
                 (n0 + n < c3H && k + 4 <= cIN) ? 16 : 0);
        }
    };

    load_stage(0, 0);
    cp_commit();

    for (int kt = 0; kt < KT; kt++) {
        if (kt + 1 < KT) {
            load_stage((kt + 1) & 1, (kt + 1) * 32);
            cp_commit();
            cp_wait<1>();
        } else {
            cp_wait<0>();
        }
        __syncthreads();
        float* A = As + (kt & 1) * 4608;
        float* B = Bs + (kt & 1) * 2304;
        #pragma unroll
        for (int kk = 0; kk < 32; kk += 8) {
            FragA a0, a1; FragBc b0, b1;
            wmma::load_matrix_sync(a0, &A[(wm * 32) * 36 + kk], 36);
            wmma::load_matrix_sync(a1, &A[(wm * 32 + 16) * 36 + kk], 36);
            wmma::load_matrix_sync(b0, &B[(wn * 32) * 36 + kk], 36);
            wmma::load_matrix_sync(b1, &B[(wn * 32 + 16) * 36 + kk], 36);
            cvt_frag(a0); cvt_frag(a1); cvt_frag(b0); cvt_frag(b1);
            wmma::mma_sync(acc[0][0], a0, b0, acc[0][0]);
            wmma::mma_sync(acc[0][1], a0, b1, acc[0][1]);
            wmma::mma_sync(acc[1][0], a1, b0, acc[1][0]);
            wmma::mma_sync(acc[1][1], a1, b1, acc[1][1]);
        }
        __syncthreads();
    }

    #pragma unroll
    for (int i = 0; i < 2; i++)
        #pragma unroll
        for (int j = 0; j < 2; j++)
            wmma::store_matrix_sync(&Cs[(wm * 32 + i * 16) * 68 + wn * 32 + j * 16],
                                    acc[i][j], 68, wmma::mem_row_major);
    __syncthreads();

    #pragma unroll
    for (int q = 0; q < 32; q++) {
        int idx = q * 256 + tid;
        int r = idx >> 6, c = idx & 63;
        int n = n0 + c;
        if (n < c3H) {
            int m = m0 + r;
            size_t crow = (size_t)(m & (cT - 1)) * cB + (m >> 6);
            dst[crow * c3H + n] = Cs[r * 68 + c] + bias[n];
        }
    }
}

// ---------------------------------------------------------------------------
// Attention GEMM (NN), tanh epilogue. N=K=460.
// ---------------------------------------------------------------------------
template <int SEL>
__global__ void __launch_bounds__(256, 2) attn_gemm_kernel(
    const float* __restrict__ Bw, const float* __restrict__ bias)
{
    const float* __restrict__ A = (SEL == 2) ? g_out : g_wv;
    float* __restrict__ C       = (SEL == 2) ? g_u   : g_u2;
    constexpr int N = c2H, K = c2H;

    extern __shared__ float sm[];
    float* As = sm;            // [2][128][36]
    float* Bs = sm + 9216;     // [2][32][68]
    float* Cs = sm;            // [128][68]

    const int n0 = blockIdx.x * 64;
    const int m0 = blockIdx.y * 128;
    const int tid = threadIdx.x;
    const int wid = tid >> 5;
    const int wm = wid & 3;
    const int wn = wid >> 2;

    constexpr int KT = (K + 31) / 32;   // 15

    FragC acc[2][2];
    #pragma unroll
    for (int i = 0; i < 2; i++)
        #pragma unroll
        for (int j = 0; j < 2; j++) wmma::fill_fragment(acc[i][j], 0.f);

    auto load_stage = [&](int st, int k0) {
        float* Ab = As + st * 4608;
        float* Bb = Bs + st * 2176;
        #pragma unroll
        for (int q = 0; q < 4; q++) {
            int idx = q * 256 + tid;
            int r = idx >> 3, c4 = idx & 7;
            int k = k0 + c4 * 4;
            cp16(smem_u32(&Ab[r * 36 + c4 * 4]),
                 A + (size_t)(m0 + r) * K + min(k, K - 4),
                 (k + 4 <= K) ? 16 : 0);
        }
        #pragma unroll
        for (int q = 0; q < 2; q++) {
            int idx = q * 256 + tid;
            int k = idx >> 4, n4 = idx & 15;
            int kk = k0 + k;
            int n = n0 + n4 * 4;
            cp16(smem_u32(&Bb[k * 68 + n4 * 4]),
                 Bw + (size_t)min(kk, K - 1) * N + min(n, N - 4),
                 (kk < K && n + 4 <= N) ? 16 : 0);
        }
    };

    load_stage(0, 0);
    cp_commit();

    for (int kt = 0; kt < KT; kt++) {
        if (kt + 1 < KT) {
            load_stage((kt + 1) & 1, (kt + 1) * 32);
            cp_commit();
            cp_wait<1>();
        } else {
            cp_wait<0>();
        }
        __syncthreads();
        float* Ab = As + (kt & 1) * 4608;
        float* Bb = Bs + (kt & 1) * 2176;
        #pragma unroll
        for (int kk = 0; kk < 32; kk += 8) {
            FragA a0, a1; FragBr b0, b1;
            wmma::load_matrix_sync(a0, &Ab[(wm * 32) * 36 + kk], 36);
            wmma::load_matrix_sync(a1, &Ab[(wm * 32 + 16) * 36 + kk], 36);
            wmma::load_matrix_sync(b0, &Bb[kk * 68 + wn * 32], 68);
            wmma::load_matrix_sync(b1, &Bb[kk * 68 + wn * 32 + 16], 68);
            cvt_frag(a0); cvt_frag(a1); cvt_frag(b0); cvt_frag(b1);
            wmma::mma_sync(acc[0][0], a0, b0, acc[0][0]);
            wmma::mma_sync(acc[0][1], a0, b1, acc[0][1]);
            wmma::mma_sync(acc[1][0], a1, b0, acc[1][0]);
            wmma::mma_sync(acc[1][1], a1, b1, acc[1][1]);
        }
        __syncthreads();
    }

    #pragma unroll
    for (int i = 0; i < 2; i++)
        #pragma unroll
        for (int j = 0; j < 2; j++)
            wmma::store_matrix_sync(&Cs[(wm * 32 + i * 16) * 68 + wn * 32 + j * 16],
                                    acc[i][j], 68, wmma::mem_row_major);
    __syncthreads();

    #pragma unroll
    for (int q = 0; q < 32; q++) {
        int idx = q * 256 + tid;
        int r = idx >> 6, c = idx & 63;
        int n = n0 + c;
        if (n < N)
            C[(size_t)(m0 + r) * N + n] = tanhf(Cs[r * 68 + c] + bias[n]);
    }
}

// ---------------------------------------------------------------------------
// Persistent GRU: one CTA owns (64-batch tile, dir) for ALL 64 time steps.
// Grid (64, 2) = 128 CTAs = single wave. No inter-CTA dependencies.
// smem: hs[64][232] (tf32 mma operand) + hex[64][232] (exact h) + warp slabs.
// W_hh read per step from L2 via g_Wt (k-major, coalesced B-frag loads).
// Warp w owns j-columns [32w, 32w+32) for all 3 gates and all 64 rows.
// ---------------------------------------------------------------------------
constexpr int GRU_SMEM = (2 * BT * cHP + 8 * 16 * 52) * sizeof(float);  // 145408

__global__ void __launch_bounds__(256, 1) gru_persistent_kernel(
    const float* __restrict__ bhh_f, const float* __restrict__ bhh_r)
{
    const int dir = blockIdx.y;
    const int b0 = blockIdx.x * BT;
    const float* __restrict__ xg  = dir ? g_xg_r : g_xg_f;
    const float* __restrict__ bhh = dir ? bhh_r : bhh_f;
    const float* __restrict__ Wd  = g_Wt[dir];

    extern __shared__ float sm[];
    float* hs  = sm;                       // [BT][cHP] tf32-rounded h
    float* hex = sm + BT * cHP;            // [BT][cHP] exact h
    const int tid = threadIdx.x;
    const int wid = tid >> 5;
    const int lane = tid & 31;
    float* slab = sm + 2 * BT * cHP + wid * (16 * 52);

    for (int i = tid; i < BT * cHP; i += 256) { hs[i] = 0.f; hex[i] = 0.f; }
    __syncthreads();

    for (int s = 0; s < cT; s++) {
        const int t = dir ? (cT - 1 - s) : s;

        #pragma unroll
        for (int p = 0; p < 2; p++) {
            const int jt = wid * 2 + p;       // j-tile index, 16 j each
            if (jt < 15) {                    // 15 tiles cover 240 >= 230
                FragC acc[3][4];
                #pragma unroll
                for (int g = 0; g < 3; g++)
                    #pragma unroll
                    for (int m = 0; m < 4; m++) wmma::fill_fragment(acc[g][m], 0.f);

                for (int k = 0; k < cHP; k += 8) {
                    FragBr bf[3];
                    #pragma unroll
                    for (int g = 0; g < 3; g++)
                        wmma::load_matrix_sync(bf[g], Wd + (size_t)k * cNW + g * cGP + jt * 16, cNW);
                    FragA af[4];
                    #pragma unroll
                    for (int m = 0; m < 4; m++)
                        wmma::load_matrix_sync(af[m], hs + (m * 16) * cHP + k, cHP);
                    #pragma unroll
                    for (int g = 0; g < 3; g++)
                        #pragma unroll
                        for (int m = 0; m < 4; m++)
                            wmma::mma_sync(acc[g][m], af[m], bf[g], acc[g][m]);
                }

                // gate epilogue: combine r/z/n per (b, j) inside the warp
                #pragma unroll
                for (int m = 0; m < 4; m++) {
                    wmma::store_matrix_sync(slab +  0, acc[0][m], 52, wmma::mem_row_major);
                    wmma::store_matrix_sync(slab + 16, acc[1][m], 52, wmma::mem_row_major);
                    wmma::store_matrix_sync(slab + 32, acc[2][m], 52, wmma::mem_row_major);
                    __syncwarp();
                    #pragma unroll
                    for (int e = 0; e < 8; e++) {
                        int idx = e * 32 + lane;
                        int rr = idx >> 4, cc = idx & 15;
                        int j = jt * 16 + cc;
                        if (j < cH) {
                            int bl = m * 16 + rr;
                            int b = b0 + bl;
                            const float* xrow = xg + ((size_t)t * cB + b) * c3H;
                            float hgr = slab[rr * 52 + cc];
                            float hgz = slab[rr * 52 + 16 + cc];
                            float hgn = slab[rr * 52 + 32 + cc];
                            float r = sigmoidf(xrow[j]          + hgr + bhh[j]);
                            float z = sigmoidf(xrow[cH + j]     + hgz + bhh[cH + j]);
                            float n = tanhf(xrow[2 * cH + j] + r * (hgn + bhh[2 * cH + j]));
                            float hold = hex[bl * cHP + j];
                            float h2 = (1.f - z) * n + z * hold;
                            hex[bl * cHP + j] = h2;
                            g_out[((size_t)t * cB + b) * c2H + dir * cH + j] = h2;
                        }
                    }
                    __syncwarp();
                }
            }
        }
        __syncthreads();   // all warps done reading hs + writing hex
        for (int i = tid; i < BT * cHP; i += 256) hs[i] = to_tf32(hex[i]);
        __syncthreads();   // hs ready for next step
    }
}

// ---------------------------------------------------------------------------
// score reductions / softmax / weighted sums / fc
// ---------------------------------------------------------------------------
template <int SEL2>
__global__ void rowdot_kernel(const float* __restrict__ proj, int M, int N) {
    int row = blockIdx.x * 8 + (threadIdx.x >> 5);
    if (row >= M) return;
    int lane = threadIdx.x & 31;
    const float* __restrict__ U = (SEL2 == 0) ? g_u : g_u2;
    const float* u = U + (size_t)row * N;
    float s = 0.f;
    for (int j = lane; j < N; j += 32) s += u[j] * proj[j];
    #pragma unroll
    for (int o = 16; o; o >>= 1) s += __shfl_xor_sync(0xffffffffu, s, o);
    if (lane == 0) {
        if (SEL2 == 0) {
            int tt = row >> 12;
            int b  = row & (cB - 1);
            g_score[(size_t)b * cT + tt] = s;
        } else {
            g_s2[row] = s;
        }
    }
}

__global__ void softmaxT_kernel() {
    int b = blockIdx.x * 8 + (threadIdx.x >> 5);
    int lane = threadIdx.x & 31;
    const float* s = g_score + (size_t)b * cT;
    float v0 = s[lane], v1 = s[lane + 32];
    float m = fmaxf(v0, v1);
    #pragma unroll
    for (int o = 16; o; o >>= 1) m = fmaxf(m, __shfl_xor_sync(0xffffffffu, m, o));
    float e0 = expf(v0 - m), e1 = expf(v1 - m);
    float sum = e0 + e1;
    #pragma unroll
    for (int o = 16; o; o >>= 1) sum += __shfl_xor_sync(0xffffffffu, sum, o);
    float inv = 1.f / sum;
    g_alpha[(size_t)b * cT + lane] = e0 * inv;
    g_alpha[(size_t)b * cT + lane + 32] = e1 * inv;
}

__global__ void wordvec_kernel() {
    int b = blockIdx.y;
    int h = blockIdx.x * 128 + threadIdx.x;
    if (h >= c2H) return;
    const float* al = g_alpha + (size_t)b * cT;
    float s = 0.f;
    for (int t = 0; t < cT; t++)
        s += al[t] * g_out[((size_t)t * cB + b) * c2H + h];
    g_wv[(size_t)b * c2H + h] = s;
}

__global__ void sentvec_kernel() {
    int nb = blockIdx.x;
    __shared__ float beta[cMS];
    if (threadIdx.x == 0) {
        float v[cMS];
        float m = -1e30f;
        for (int ms = 0; ms < cMS; ms++) { v[ms] = g_s2[nb * cMS + ms]; m = fmaxf(m, v[ms]); }
        float sum = 0.f;
        for (int ms = 0; ms < cMS; ms++) { v[ms] = expf(v[ms] - m); sum += v[ms]; }
        float inv = 1.f / sum;
        for (int ms = 0; ms < cMS; ms++) beta[ms] = v[ms] * inv;
    }
    __syncthreads();
    for (int h = threadIdx.x; h < c2H; h += blockDim.x) {
        float s = 0.f;
        #pragma unroll
        for (int ms = 0; ms < cMS; ms++)
            s += beta[ms] * g_wv[((size_t)nb * cMS + ms) * c2H + h];
        g_sent[(size_t)nb * c2H + h] = s;
    }
}

__global__ void fc_scatter_kernel(const float* __restrict__ fcW,
                                  const float* __restrict__ fcb,
                                  const int* __restrict__ pairs,
                                  float* __restrict__ out)
{
    int nb = blockIdx.x;
    __shared__ float sv[c2H];
    for (int k = threadIdx.x; k < c2H; k += blockDim.x)
        sv[k] = g_sent[(size_t)nb * c2H + k];
    __syncthreads();
    int o = threadIdx.x;
    if (o < cOUT) {
        const float* w = fcW + (size_t)o * c2H;
        float s = fcb[o];
        for (int k = 0; k < c2H; k++) s += sv[k] * w[k];
        int d  = pairs[nb * 3 + 0];
        int e1 = pairs[nb * 3 + 1];
        int e2 = pairs[nb * 3 + 2];
        out[(((size_t)d * cENT + e1) * cENT + e2) * cOUT + o] = s;
    }
}

// ---------------------------------------------------------------------------
extern "C" void kernel_launch(void* const* d_in, const int* in_sizes, int n_in,
                              void* d_out, int out_size) {
    const float* bag   = (const float*)d_in[0];
    const float* Wihf  = (const float*)d_in[1];
    const float* Whhf  = (const float*)d_in[2];
    const float* bihf  = (const float*)d_in[3];
    const float* bhhf  = (const float*)d_in[4];
    const float* Wihr  = (const float*)d_in[5];
    const float* Whhr  = (const float*)d_in[6];
    const float* bihr  = (const float*)d_in[7];
    const float* bhhr  = (const float*)d_in[8];
    const float* Wword = (const float*)d_in[9];
    const float* bword = (const float*)d_in[10];
    const float* pjw   = (const float*)d_in[11];
    const float* Wsent = (const float*)d_in[12];
    const float* bsent = (const float*)d_in[13];
    const float* pjs   = (const float*)d_in[14];
    const float* fcW   = (const float*)d_in[15];
    const float* fcb   = (const float*)d_in[16];
    const int*   pairs = (const int*)d_in[17];
    float* out = (float*)d_out;

    constexpr int smem_iproj = (2 * 128 * 36 + 2 * 64 * 36) * 4;   // 55296
    constexpr int smem_attn  = (2 * 128 * 36 + 2 * 32 * 68) * 4;   // 54272

    static int attr_done = 0;
    if (!attr_done) {
        cudaFuncSetAttribute(iproj_kernel, cudaFuncAttributeMaxDynamicSharedMemorySize, smem_iproj);
        cudaFuncSetAttribute(attn_gemm_kernel<2>, cudaFuncAttributeMaxDynamicSharedMemorySize, smem_attn);
        cudaFuncSetAttribute(attn_gemm_kernel<3>, cudaFuncAttributeMaxDynamicSharedMemorySize, smem_attn);
        cudaFuncSetAttribute(gru_persistent_kernel, cudaFuncAttributeMaxDynamicSharedMemorySize, GRU_SMEM);
        attr_done = 1;
    }

    zero_out_kernel<<<(out_size + 255) / 256, 256>>>(out, out_size);
    wt_prep_kernel<<<(2 * 232 * cNW + 255) / 256, 256>>>(Whhf, Whhr);

    // input projections (both dirs)
    {
        dim3 grid((c3H + 63) / 64, (int)(cTB / 128), 2);
        iproj_kernel<<<grid, 256, smem_iproj>>>(bag, Wihf, bihf, Wihr, bihr);
    }

    // GRU recurrence: single persistent launch, 128 CTAs = one wave
    {
        dim3 grid(cB / BT, 2);
        gru_persistent_kernel<<<grid, 256, GRU_SMEM>>>(bhhf, bhhr);
    }

    // word attention
    {
        dim3 grid((c2H + 63) / 64, (int)(cTB / 128));
        attn_gemm_kernel<2><<<grid, 256, smem_attn>>>(Wword, bword);
    }
    rowdot_kernel<0><<<(int)(cTB / 8), 256>>>(pjw, (int)cTB, c2H);
    softmaxT_kernel<<<cB / 8, 256>>>();
    {
        dim3 grid((c2H + 127) / 128, cB);
        wordvec_kernel<<<grid, 128>>>();
    }

    // sentence attention
    {
        dim3 grid((c2H + 63) / 64, cB / 128);
        attn_gemm_kernel<3><<<grid, 256, smem_attn>>>(Wsent, bsent);
    }
    rowdot_kernel<1><<<cB / 8, 256>>>(pjs, cB, c2H);
    sentvec_kernel<<<cNB, 128>>>();

    fc_scatter_kernel<<<cNB, 64>>>(fcW, fcb, pairs, out);
}

// round 6
// speedup vs baseline: 1.0601x; 1.0601x over previous
#include <cuda_runtime.h>
#include <mma.h>
#include <math.h>
#include <cstdint>

using namespace nvcuda;

// Problem constants
constexpr int cNB   = 512;
constexpr int cMS   = 8;
constexpr int cT    = 64;
constexpr int cIN   = 360;
constexpr int cH    = 230;
constexpr int cOUT  = 53;
constexpr int cENT  = 8;
constexpr int cB    = cNB * cMS;     // 4096
constexpr int c3H   = 3 * cH;        // 690
constexpr int c2H   = 2 * cH;        // 460
constexpr size_t cTB = (size_t)cT * cB;   // 262144

constexpr int cGP   = 240;           // per-gate padded width in Wt
constexpr int cNW   = 3 * cGP;       // 720 (Wt n-dim)
constexpr int cKP   = 232;           // padded K (hidden) for mma
constexpr int BT    = 64;            // batch tile per GRU CTA
constexpr int cHS   = 236;           // hs/hex smem row stride (bank-stagger)
constexpr int cWS   = 724;           // W stage smem row stride

// ---------------------------------------------------------------------------
// Scratch
// ---------------------------------------------------------------------------
static __device__ float g_xg_f[(size_t)cT * cB * c3H];  // [T][B][3H]
static __device__ float g_xg_r[(size_t)cT * cB * c3H];
static __device__ float g_out [(size_t)cT * cB * c2H];  // [T][B][2H]
static __device__ float g_u   [(size_t)cT * cB * c2H];
static __device__ float g_Wt  [2][cKP * cNW];           // k-major padded tf32 W_hh
static __device__ float g_score[(size_t)cB * cT];
static __device__ float g_alpha[(size_t)cB * cT];
static __device__ float g_wv  [(size_t)cB * c2H];
static __device__ float g_u2  [(size_t)cB * c2H];
static __device__ float g_s2  [cB];
static __device__ float g_sent[(size_t)cNB * c2H];

// ---------------------------------------------------------------------------
// Helpers
// ---------------------------------------------------------------------------
__device__ __forceinline__ float to_tf32(float x) {
    float r;
    asm("cvt.rna.tf32.f32 %0, %1;\n" : "=f"(r) : "f"(x));
    return r;
}
__device__ __forceinline__ float sigmoidf(float x) {
    return 1.f / (1.f + expf(-x));
}
__device__ __forceinline__ unsigned int smem_u32(const void* p) {
    return (unsigned int)__cvta_generic_to_shared(p);
}
__device__ __forceinline__ void cp16(unsigned int d, const void* s, int srcsize) {
    asm volatile("cp.async.cg.shared.global [%0], [%1], 16, %2;\n"
                 :: "r"(d), "l"(s), "r"(srcsize));
}
__device__ __forceinline__ void cp16f(unsigned int d, const void* s) {
    asm volatile("cp.async.cg.shared.global [%0], [%1], 16;\n"
                 :: "r"(d), "l"(s));
}
__device__ __forceinline__ void cp_commit() {
    asm volatile("cp.async.commit_group;\n");
}
template <int N>
__device__ __forceinline__ void cp_wait() {
    asm volatile("cp.async.wait_group %0;\n" :: "n"(N));
}
__device__ __forceinline__ void l2_prefetch(const void* p) {
    asm volatile("prefetch.global.L2 [%0];" :: "l"(p));
}

typedef wmma::fragment<wmma::matrix_a, 16, 16, 8, wmma::precision::tf32, wmma::row_major> FragA;
typedef wmma::fragment<wmma::matrix_b, 16, 16, 8, wmma::precision::tf32, wmma::col_major> FragBc;
typedef wmma::fragment<wmma::matrix_b, 16, 16, 8, wmma::precision::tf32, wmma::row_major> FragBr;
typedef wmma::fragment<wmma::accumulator, 16, 16, 8, float> FragC;

template <class F>
__device__ __forceinline__ void cvt_frag(F& f) {
    #pragma unroll
    for (int i = 0; i < f.num_elements; i++) f.x[i] = to_tf32(f.x[i]);
}

// ---------------------------------------------------------------------------
// Utility kernels
// ---------------------------------------------------------------------------
__global__ void zero_out_kernel(float* p, int n) {
    int i = blockIdx.x * blockDim.x + threadIdx.x;
    if (i < n) p[i] = 0.f;
}

// g_Wt[dir][k][g*240 + j] = tf32(Whh[g*230 + j][k]); zero padding elsewhere.
__global__ void wt_prep_kernel(const float* __restrict__ Whhf,
                               const float* __restrict__ Whhr) {
    int i = blockIdx.x * blockDim.x + threadIdx.x;
    if (i >= 2 * cKP * cNW) return;
    int dir = i / (cKP * cNW);
    int r = i % (cKP * cNW);
    int k = r / cNW, n = r % cNW;
    int g = n / cGP, j = n % cGP;
    const float* W = dir ? Whhr : Whhf;
    float v = 0.f;
    if (j < cH && k < cH) v = to_tf32(W[(size_t)(g * cH + j) * cH + k]);
    g_Wt[dir][(size_t)k * cNW + n] = v;
}

// ---------------------------------------------------------------------------
// Input projection: C[M=262144, N=690] = bag @ W^T + b  (TN), row remap.
// ---------------------------------------------------------------------------
__global__ void __launch_bounds__(256, 2) iproj_kernel(
    const float* __restrict__ bag,
    const float* __restrict__ Wf, const float* __restrict__ bf,
    const float* __restrict__ Wr, const float* __restrict__ br)
{
    const int z = blockIdx.z;
    const float* __restrict__ W    = z ? Wr : Wf;
    const float* __restrict__ bias = z ? br : bf;
    float* __restrict__ dst        = z ? g_xg_r : g_xg_f;

    extern __shared__ float sm[];
    float* As = sm;            // [2][128][36]
    float* Bs = sm + 9216;     // [2][64][36]
    float* Cs = sm;            // [128][68]

    const int n0 = blockIdx.x * 64;
    const int m0 = blockIdx.y * 128;
    const int tid = threadIdx.x;
    const int wid = tid >> 5;
    const int wm = wid & 3;
    const int wn = wid >> 2;

    constexpr int KT = (cIN + 31) / 32;   // 12

    FragC acc[2][2];
    #pragma unroll
    for (int i = 0; i < 2; i++)
        #pragma unroll
        for (int j = 0; j < 2; j++) wmma::fill_fragment(acc[i][j], 0.f);

    auto load_stage = [&](int st, int k0) {
        float* A = As + st * 4608;
        float* B = Bs + st * 2304;
        #pragma unroll
        for (int q = 0; q < 4; q++) {
            int idx = q * 256 + tid;
            int r = idx >> 3, c4 = idx & 7;
            int k = k0 + c4 * 4;
            cp16(smem_u32(&A[r * 36 + c4 * 4]),
                 bag + (size_t)(m0 + r) * cIN + min(k, cIN - 4),
                 (k + 4 <= cIN) ? 16 : 0);
        }
        #pragma unroll
        for (int q = 0; q < 2; q++) {
            int idx = q * 256 + tid;
            int n = idx >> 3, c4 = idx & 7;
            int k = k0 + c4 * 4;
            int nn = min(n0 + n, c3H - 1);
            cp16(smem_u32(&B[n * 36 + c4 * 4]),
                 W + (size_t)nn * cIN + min(k, cIN - 4),
                 (n0 + n < c3H && k + 4 <= cIN) ? 16 : 0);
        }
    };

    load_stage(0, 0);
    cp_commit();

    for (int kt = 0; kt < KT; kt++) {
        if (kt + 1 < KT) {
            load_stage((kt + 1) & 1, (kt + 1) * 32);
            cp_commit();
            cp_wait<1>();
        } else {
            cp_wait<0>();
        }
        __syncthreads();
        float* A = As + (kt & 1) * 4608;
        float* B = Bs + (kt & 1) * 2304;
        #pragma unroll
        for (int kk = 0; kk < 32; kk += 8) {
            FragA a0, a1; FragBc b0, b1;
            wmma::load_matrix_sync(a0, &A[(wm * 32) * 36 + kk], 36);
            wmma::load_matrix_sync(a1, &A[(wm * 32 + 16) * 36 + kk], 36);
            wmma::load_matrix_sync(b0, &B[(wn * 32) * 36 + kk], 36);
            wmma::load_matrix_sync(b1, &B[(wn * 32 + 16) * 36 + kk], 36);
            cvt_frag(a0); cvt_frag(a1); cvt_frag(b0); cvt_frag(b1);
            wmma::mma_sync(acc[0][0], a0, b0, acc[0][0]);
            wmma::mma_sync(acc[0][1], a0, b1, acc[0][1]);
            wmma::mma_sync(acc[1][0], a1, b0, acc[1][0]);
            wmma::mma_sync(acc[1][1], a1, b1, acc[1][1]);
        }
        __syncthreads();
    }

    #pragma unroll
    for (int i = 0; i < 2; i++)
        #pragma unroll
        for (int j = 0; j < 2; j++)
            wmma::store_matrix_sync(&Cs[(wm * 32 + i * 16) * 68 + wn * 32 + j * 16],
                                    acc[i][j], 68, wmma::mem_row_major);
    __syncthreads();

    #pragma unroll
    for (int q = 0; q < 32; q++) {
        int idx = q * 256 + tid;
        int r = idx >> 6, c = idx & 63;
        int n = n0 + c;
        if (n < c3H) {
            int m = m0 + r;
            size_t crow = (size_t)(m & (cT - 1)) * cB + (m >> 6);
            dst[crow * c3H + n] = Cs[r * 68 + c] + bias[n];
        }
    }
}

// ---------------------------------------------------------------------------
// Attention GEMM (NN), tanh epilogue. N=K=460.
// ---------------------------------------------------------------------------
template <int SEL>
__global__ void __launch_bounds__(256, 2) attn_gemm_kernel(
    const float* __restrict__ Bw, const float* __restrict__ bias)
{
    const float* __restrict__ A = (SEL == 2) ? g_out : g_wv;
    float* __restrict__ C       = (SEL == 2) ? g_u   : g_u2;
    constexpr int N = c2H, K = c2H;

    extern __shared__ float sm[];
    float* As = sm;            // [2][128][36]
    float* Bs = sm + 9216;     // [2][32][68]
    float* Cs = sm;            // [128][68]

    const int n0 = blockIdx.x * 64;
    const int m0 = blockIdx.y * 128;
    const int tid = threadIdx.x;
    const int wid = tid >> 5;
    const int wm = wid & 3;
    const int wn = wid >> 2;

    constexpr int KT = (K + 31) / 32;   // 15

    FragC acc[2][2];
    #pragma unroll
    for (int i = 0; i < 2; i++)
        #pragma unroll
        for (int j = 0; j < 2; j++) wmma::fill_fragment(acc[i][j], 0.f);

    auto load_stage = [&](int st, int k0) {
        float* Ab = As + st * 4608;
        float* Bb = Bs + st * 2176;
        #pragma unroll
        for (int q = 0; q < 4; q++) {
            int idx = q * 256 + tid;
            int r = idx >> 3, c4 = idx & 7;
            int k = k0 + c4 * 4;
            cp16(smem_u32(&Ab[r * 36 + c4 * 4]),
                 A + (size_t)(m0 + r) * K + min(k, K - 4),
                 (k + 4 <= K) ? 16 : 0);
        }
        #pragma unroll
        for (int q = 0; q < 2; q++) {
            int idx = q * 256 + tid;
            int k = idx >> 4, n4 = idx & 15;
            int kk = k0 + k;
            int n = n0 + n4 * 4;
            cp16(smem_u32(&Bb[k * 68 + n4 * 4]),
                 Bw + (size_t)min(kk, K - 1) * N + min(n, N - 4),
                 (kk < K && n + 4 <= N) ? 16 : 0);
        }
    };

    load_stage(0, 0);
    cp_commit();

    for (int kt = 0; kt < KT; kt++) {
        if (kt + 1 < KT) {
            load_stage((kt + 1) & 1, (kt + 1) * 32);
            cp_commit();
            cp_wait<1>();
        } else {
            cp_wait<0>();
        }
        __syncthreads();
        float* Ab = As + (kt & 1) * 4608;
        float* Bb = Bs + (kt & 1) * 2176;
        #pragma unroll
        for (int kk = 0; kk < 32; kk += 8) {
            FragA a0, a1; FragBr b0, b1;
            wmma::load_matrix_sync(a0, &Ab[(wm * 32) * 36 + kk], 36);
            wmma::load_matrix_sync(a1, &Ab[(wm * 32 + 16) * 36 + kk], 36);
            wmma::load_matrix_sync(b0, &Bb[kk * 68 + wn * 32], 68);
            wmma::load_matrix_sync(b1, &Bb[kk * 68 + wn * 32 + 16], 68);
            cvt_frag(a0); cvt_frag(a1); cvt_frag(b0); cvt_frag(b1);
            wmma::mma_sync(acc[0][0], a0, b0, acc[0][0]);
            wmma::mma_sync(acc[0][1], a0, b1, acc[0][1]);
            wmma::mma_sync(acc[1][0], a1, b0, acc[1][0]);
            wmma::mma_sync(acc[1][1], a1, b1, acc[1][1]);
        }
        __syncthreads();
    }

    #pragma unroll
    for (int i = 0; i < 2; i++)
        #pragma unroll
        for (int j = 0; j < 2; j++)
            wmma::store_matrix_sync(&Cs[(wm * 32 + i * 16) * 68 + wn * 32 + j * 16],
                                    acc[i][j], 68, wmma::mem_row_major);
    __syncthreads();

    #pragma unroll
    for (int q = 0; q < 32; q++) {
        int idx = q * 256 + tid;
        int r = idx >> 6, c = idx & 63;
        int n = n0 + c;
        if (n < N)
            C[(size_t)(m0 + r) * N + n] = tanhf(Cs[r * 68 + c] + bias[n]);
    }
}

// ---------------------------------------------------------------------------
// Persistent GRU v2: one CTA per (64-batch tile, dir), all 64 steps.
// W streamed L2 -> smem via double-buffered cp.async in k-chunks of 8.
// smem: hs[64][236] tf32 h, hex[64][236] exact h, Wst[2][8][724], slabs.
// Warp w owns j-tiles {2w, 2w+1} (16 j each) for all 3 gates, all 64 rows.
// ---------------------------------------------------------------------------
constexpr int GRU_HS    = BT * cHS;              // 15104 floats
constexpr int GRU_WST1  = 8 * cWS;               // 5792 floats (one stage)
constexpr int GRU_SLAB  = 16 * 52;               // 832 floats per warp
constexpr int GRU_SMEMF = 2 * GRU_HS + 2 * GRU_WST1 + 8 * GRU_SLAB;  // 48448
constexpr int GRU_SMEM  = GRU_SMEMF * 4;         // 193792 bytes

__global__ void __launch_bounds__(256, 1) gru_persistent_kernel(
    const float* __restrict__ bhh_f, const float* __restrict__ bhh_r)
{
    const int dir = blockIdx.y;
    const int b0 = blockIdx.x * BT;
    const float* __restrict__ xg  = dir ? g_xg_r : g_xg_f;
    const float* __restrict__ bhh = dir ? bhh_r : bhh_f;
    const float* __restrict__ Wd  = g_Wt[dir];

    extern __shared__ float sm[];
    float* hs   = sm;                        // [64][236]
    float* hex  = sm + GRU_HS;               // [64][236]
    float* Wst  = sm + 2 * GRU_HS;           // [2][8][724]
    const int tid = threadIdx.x;
    const int wid = tid >> 5;
    const int lane = tid & 31;
    float* slab = sm + 2 * GRU_HS + 2 * GRU_WST1 + wid * GRU_SLAB;

    for (int i = tid; i < 2 * GRU_HS; i += 256) sm[i] = 0.f;

    // stage W rows [k0, k0+8) into buffer buf (1440 cp16 ops)
    auto stage = [&](int buf, int k0) {
        const float* src = Wd + (size_t)k0 * cNW;
        float* dstW = Wst + buf * GRU_WST1;
        #pragma unroll
        for (int q = 0; q < 6; q++) {
            int idx = q * 256 + tid;
            if (idx < 1440) {
                int r = idx / 180, c = idx % 180;
                cp16f(smem_u32(&dstW[r * cWS + c * 4]), src + r * cNW + c * 4);
            }
        }
    };

    stage(0, 0);
    cp_commit();
    __syncthreads();   // also covers hs/hex zero-init

    int gbuf = 0;
    FragC acc[2][3][4];

    for (int s = 0; s < cT; s++) {
        const int t = dir ? (cT - 1 - s) : s;

        // L2-prefetch this step's xg rows (consumed by the epilogue ~15K cyc later)
        {
            const float* base = xg + ((size_t)t * cB + b0) * c3H;
            #pragma unroll
            for (int q = 0; q < 6; q++) {
                int line = q * 256 + tid;
                if (line < 1408) {
                    int r = line / 22, c = line % 22;
                    int off = c * 32;
                    if (off < c3H) l2_prefetch(base + (size_t)r * c3H + off);
                }
            }
        }

        #pragma unroll
        for (int p = 0; p < 2; p++)
            #pragma unroll
            for (int g = 0; g < 3; g++)
                #pragma unroll
                for (int m = 0; m < 4; m++) wmma::fill_fragment(acc[p][g][m], 0.f);

        for (int c = 0; c < 29; c++) {
            const bool last = (s == cT - 1) && (c == 28);
            if (!last) {
                stage(gbuf ^ 1, (c == 28) ? 0 : (c + 1) * 8);
                cp_commit();
                cp_wait<1>();
            } else {
                cp_wait<0>();
            }
            __syncthreads();

            float* Wb = Wst + gbuf * GRU_WST1;
            const int k0 = c * 8;
            #pragma unroll
            for (int p = 0; p < 2; p++) {
                const int jt = wid * 2 + p;
                if (jt < 15) {
                    FragBr bf[3];
                    #pragma unroll
                    for (int g = 0; g < 3; g++)
                        wmma::load_matrix_sync(bf[g], Wb + g * cGP + jt * 16, cWS);
                    #pragma unroll
                    for (int m = 0; m < 4; m++) {
                        FragA af;
                        wmma::load_matrix_sync(af, hs + (m * 16) * cHS + k0, cHS);
                        #pragma unroll
                        for (int g = 0; g < 3; g++)
                            wmma::mma_sync(acc[p][g][m], af, bf[g], acc[p][g][m]);
                    }
                }
            }
            gbuf ^= 1;
            __syncthreads();   // chunk consumed; next staging may overwrite
        }

        // all mma done (post-loop barrier above) -> safe to overwrite hs
        #pragma unroll
        for (int p = 0; p < 2; p++) {
            const int jt = wid * 2 + p;
            if (jt >= 15) continue;
            #pragma unroll
            for (int m = 0; m < 4; m++) {
                wmma::store_matrix_sync(slab +  0, acc[p][0][m], 52, wmma::mem_row_major);
                wmma::store_matrix_sync(slab + 16, acc[p][1][m], 52, wmma::mem_row_major);
                wmma::store_matrix_sync(slab + 32, acc[p][2][m], 52, wmma::mem_row_major);
                __syncwarp();
                #pragma unroll
                for (int e = 0; e < 8; e++) {
                    int idx = e * 32 + lane;
                    int rr = idx >> 4, cc = idx & 15;
                    int j = jt * 16 + cc;
                    if (j < cH) {
                        int bl = m * 16 + rr;
                        int b = b0 + bl;
                        const float* xrow = xg + ((size_t)t * cB + b) * c3H;
                        float hgr = slab[rr * 52 + cc];
                        float hgz = slab[rr * 52 + 16 + cc];
                        float hgn = slab[rr * 52 + 32 + cc];
                        float r = sigmoidf(xrow[j]          + hgr + bhh[j]);
                        float z = sigmoidf(xrow[cH + j]     + hgz + bhh[cH + j]);
                        float n = tanhf(xrow[2 * cH + j] + r * (hgn + bhh[2 * cH + j]));
                        float hold = hex[bl * cHS + j];
                        float h2 = (1.f - z) * n + z * hold;
                        hex[bl * cHS + j] = h2;
                        hs[bl * cHS + j] = to_tf32(h2);
                        g_out[((size_t)t * cB + b) * c2H + dir * cH + j] = h2;
                    }
                }
                __syncwarp();
            }
        }
        __syncthreads();   // hs(t+1) ready before next step's mma reads it
    }
}

// ---------------------------------------------------------------------------
// score reductions / softmax / weighted sums / fc
// ---------------------------------------------------------------------------
template <int SEL2>
__global__ void rowdot_kernel(const float* __restrict__ proj, int M, int N) {
    int row = blockIdx.x * 8 + (threadIdx.x >> 5);
    if (row >= M) return;
    int lane = threadIdx.x & 31;
    const float* __restrict__ U = (SEL2 == 0) ? g_u : g_u2;
    const float* u = U + (size_t)row * N;
    float s = 0.f;
    for (int j = lane; j < N; j += 32) s += u[j] * proj[j];
    #pragma unroll
    for (int o = 16; o; o >>= 1) s += __shfl_xor_sync(0xffffffffu, s, o);
    if (lane == 0) {
        if (SEL2 == 0) {
            int tt = row >> 12;
            int b  = row & (cB - 1);
            g_score[(size_t)b * cT + tt] = s;
        } else {
            g_s2[row] = s;
        }
    }
}

__global__ void softmaxT_kernel() {
    int b = blockIdx.x * 8 + (threadIdx.x >> 5);
    int lane = threadIdx.x & 31;
    const float* s = g_score + (size_t)b * cT;
    float v0 = s[lane], v1 = s[lane + 32];
    float m = fmaxf(v0, v1);
    #pragma unroll
    for (int o = 16; o; o >>= 1) m = fmaxf(m, __shfl_xor_sync(0xffffffffu, m, o));
    float e0 = expf(v0 - m), e1 = expf(v1 - m);
    float sum = e0 + e1;
    #pragma unroll
    for (int o = 16; o; o >>= 1) sum += __shfl_xor_sync(0xffffffffu, sum, o);
    float inv = 1.f / sum;
    g_alpha[(size_t)b * cT + lane] = e0 * inv;
    g_alpha[(size_t)b * cT + lane + 32] = e1 * inv;
}

__global__ void wordvec_kernel() {
    int b = blockIdx.y;
    int h = blockIdx.x * 128 + threadIdx.x;
    if (h >= c2H) return;
    const float* al = g_alpha + (size_t)b * cT;
    float s = 0.f;
    for (int t = 0; t < cT; t++)
        s += al[t] * g_out[((size_t)t * cB + b) * c2H + h];
    g_wv[(size_t)b * c2H + h] = s;
}

__global__ void sentvec_kernel() {
    int nb = blockIdx.x;
    __shared__ float beta[cMS];
    if (threadIdx.x == 0) {
        float v[cMS];
        float m = -1e30f;
        for (int ms = 0; ms < cMS; ms++) { v[ms] = g_s2[nb * cMS + ms]; m = fmaxf(m, v[ms]); }
        float sum = 0.f;
        for (int ms = 0; ms < cMS; ms++) { v[ms] = expf(v[ms] - m); sum += v[ms]; }
        float inv = 1.f / sum;
        for (int ms = 0; ms < cMS; ms++) beta[ms] = v[ms] * inv;
    }
    __syncthreads();
    for (int h = threadIdx.x; h < c2H; h += blockDim.x) {
        float s = 0.f;
        #pragma unroll
        for (int ms = 0; ms < cMS; ms++)
            s += beta[ms] * g_wv[((size_t)nb * cMS + ms) * c2H + h];
        g_sent[(size_t)nb * c2H + h] = s;
    }
}

__global__ void fc_scatter_kernel(const float* __restrict__ fcW,
                                  const float* __restrict__ fcb,
                                  const int* __restrict__ pairs,
                                  float* __restrict__ out)
{
    int nb = blockIdx.x;
    __shared__ float sv[c2H];
    for (int k = threadIdx.x; k < c2H; k += blockDim.x)
        sv[k] = g_sent[(size_t)nb * c2H + k];
    __syncthreads();
    int o = threadIdx.x;
    if (o < cOUT) {
        const float* w = fcW + (size_t)o * c2H;
        float s = fcb[o];
        for (int k = 0; k < c2H; k++) s += sv[k] * w[k];
        int d  = pairs[nb * 3 + 0];
        int e1 = pairs[nb * 3 + 1];
        int e2 = pairs[nb * 3 + 2];
        out[(((size_t)d * cENT + e1) * cENT + e2) * cOUT + o] = s;
    }
}

// ---------------------------------------------------------------------------
extern "C" void kernel_launch(void* const* d_in, const int* in_sizes, int n_in,
                              void* d_out, int out_size) {
    const float* bag   = (const float*)d_in[0];
    const float* Wihf  = (const float*)d_in[1];
    const float* Whhf  = (const float*)d_in[2];
    const float* bihf  = (const float*)d_in[3];
    const float* bhhf  = (const float*)d_in[4];
    const float* Wihr  = (const float*)d_in[5];
    const float* Whhr  = (const float*)d_in[6];
    const float* bihr  = (const float*)d_in[7];
    const float* bhhr  = (const float*)d_in[8];
    const float* Wword = (const float*)d_in[9];
    const float* bword = (const float*)d_in[10];
    const float* pjw   = (const float*)d_in[11];
    const float* Wsent = (const float*)d_in[12];
    const float* bsent = (const float*)d_in[13];
    const float* pjs   = (const float*)d_in[14];
    const float* fcW   = (const float*)d_in[15];
    const float* fcb   = (const float*)d_in[16];
    const int*   pairs = (const int*)d_in[17];
    float* out = (float*)d_out;

    constexpr int smem_iproj = (2 * 128 * 36 + 2 * 64 * 36) * 4;   // 55296
    constexpr int smem_attn  = (2 * 128 * 36 + 2 * 32 * 68) * 4;   // 54272

    static int attr_done = 0;
    if (!attr_done) {
        cudaFuncSetAttribute(iproj_kernel, cudaFuncAttributeMaxDynamicSharedMemorySize, smem_iproj);
        cudaFuncSetAttribute(attn_gemm_kernel<2>, cudaFuncAttributeMaxDynamicSharedMemorySize, smem_attn);
        cudaFuncSetAttribute(attn_gemm_kernel<3>, cudaFuncAttributeMaxDynamicSharedMemorySize, smem_attn);
        cudaFuncSetAttribute(gru_persistent_kernel, cudaFuncAttributeMaxDynamicSharedMemorySize, GRU_SMEM);
        attr_done = 1;
    }

    zero_out_kernel<<<(out_size + 255) / 256, 256>>>(out, out_size);
    wt_prep_kernel<<<(2 * cKP * cNW + 255) / 256, 256>>>(Whhf, Whhr);

    // input projections (both dirs)
    {
        dim3 grid((c3H + 63) / 64, (int)(cTB / 128), 2);
        iproj_kernel<<<grid, 256, smem_iproj>>>(bag, Wihf, bihf, Wihr, bihr);
    }

    // GRU recurrence: single persistent launch, 128 CTAs = one wave
    {
        dim3 grid(cB / BT, 2);
        gru_persistent_kernel<<<grid, 256, GRU_SMEM>>>(bhhf, bhhr);
    }

    // word attention
    {
        dim3 grid((c2H + 63) / 64, (int)(cTB / 128));
        attn_gemm_kernel<2><<<grid, 256, smem_attn>>>(Wword, bword);
    }
    rowdot_kernel<0><<<(int)(cTB / 8), 256>>>(pjw, (int)cTB, c2H);
    softmaxT_kernel<<<cB / 8, 256>>>();
    {
        dim3 grid((c2H + 127) / 128, cB);
        wordvec_kernel<<<grid, 128>>>();
    }

    // sentence attention
    {
        dim3 grid((c2H + 63) / 64, cB / 128);
        attn_gemm_kernel<3><<<grid, 256, smem_attn>>>(Wsent, bsent);
    }
    rowdot_kernel<1><<<cB / 8, 256>>>(pjs, cB, c2H);
    sentvec_kernel<<<cNB, 128>>>();

    fc_scatter_kernel<<<cNB, 64>>>(fcW, fcb, pairs, out);
}